// round 3
// baseline (speedup 1.0000x reference)
#include <cuda_runtime.h>

// 4-qubit VQE energy, warp-parallel, Clifford-folded.
// lane = q0*8 + q1*4 + q2*2 + q3. All gates real => psi real.
//
// Leading Clifford block folded into init state: psi = +0.5 @ lanes 6,7 ; -0.5 @ lanes 10,11.
// Trailing Clifford block conjugated into the observable (Pauli masks {0,1,5,8,12,13}).
// CNOT permutations merged into adjacent H/RY layers via computed shuffle sources.

#define FULL 0xffffffffu
#define R_SQ2 0.70710678118654752f

__global__ void vqe_energy_kernel(const float* __restrict__ phi_in,
                                  float* __restrict__ out) {
    const int lane = threadIdx.x & 15;

    // ---- per-lane index maps (off critical path, overlap the LDG) ----
    const int p03   = lane ^ ((lane >> 3) & 1);                    // cnot(0,3) map
    const int p03b  = p03 ^ 1;                                     // P03(lane^1)
    const int p31   = lane ^ ((lane & 1) << 2);                    // cnot(3,1) map
    const int p31b  = (lane ^ 1) ^ (((lane ^ 1) & 1) << 2);        // P31(lane^1)
    const int q     = lane ^ ((lane & 2) ? 12 : 0);                // cnot(2,1);cnot(2,0) map
    const int p03_8 = (lane ^ 8) ^ (((lane ^ 8) >> 3) & 1);        // P03(lane^8)

    // ---- per-lane observable weights (conjugated Pauli sum) ----
    const float s0 = (lane & 8) ? -1.f : 1.f;
    const float s1 = (lane & 4) ? -1.f : 1.f;
    const float s2 = (lane & 2) ? -1.f : 1.f;
    const float s01  = s0 * s1;
    const float s012 = s01 * s2;
    const float w0  = 0.1777135822909176f * s01 + 0.12293330449299354f * s2;
    const float w1  = 0.1676833885560135f * s2 + 0.17627661394181787f;
    const float w5  = 0.04475008406301996f * (s0 * s2 - s0);
    const float w8  = 0.04475008406301996f * (s1 - s1 * s2);
    const float w12 = 0.1777135822909176f - 0.24274501260941383f * s2
                    + 0.17059759276836806f * s01 + 0.1676833885560135f * s012;
    const float w13 = -0.24274501260941383f * s2 + 0.12293330449299354f * s012;

    const float h3d = (lane & 1) ? -R_SQ2 : R_SQ2;

    // ---- phi-dependent coefficients ----
    const float phi = phi_in[0];
    float s, c;
    __sincosf(phi * 0.0625f, &s, &c);       // half-angle of ry(phi/8)
    const float cc  = c * c;
    const float o1p = (lane & 4) ?  s : -s; // ry+(q1) off-diag
    const float o0m = (lane & 8) ? -s :  s; // ry-(q0) off-diag
    const float Ap  = o1p * c;
    const float Bm  = c * o0m;
    const float Cpm = o1p * o0m;            // same for both ry-layer variants

    // ---- init (leading Cliffords folded) ----
    float psi = 0.f;
    {
        const int g = lane >> 1;            // pair id
        if (g == 3) psi = 0.5f;             // lanes 6,7
        if (g == 5) psi = -0.5f;            // lanes 10,11
    }

    // S1: ry+(1); ry-(0)
    {
        float a = __shfl_xor_sync(FULL, psi, 4, 16);
        float b = __shfl_xor_sync(FULL, psi, 8, 16);
        float d = __shfl_xor_sync(FULL, psi, 12, 16);
        psi = cc * psi + Ap * a + Bm * b + Cpm * d;
    }
    // S2: cnot(0,3) + h(3)
    {
        float x0 = __shfl_sync(FULL, psi, p03, 16);
        float x1 = __shfl_sync(FULL, psi, p03b, 16);
        psi = h3d * x0 + R_SQ2 * x1;
    }
    // S3: cnot(3,1) + [ry+(1); ry-(0)]
    {
        float x0 = __shfl_sync(FULL, psi, p31, 16);
        float xa = __shfl_sync(FULL, psi, p31 ^ 4, 16);
        float xb = __shfl_sync(FULL, psi, p31 ^ 8, 16);
        float xc = __shfl_sync(FULL, psi, p31 ^ 12, 16);
        psi = cc * x0 + Ap * xa + Bm * xb + Cpm * xc;
    }
    // S4: cnot(2,1);cnot(2,0) + [ry-(1); ry+(0)]
    {
        float x0 = __shfl_sync(FULL, psi, q, 16);
        float xa = __shfl_sync(FULL, psi, q ^ 4, 16);
        float xb = __shfl_sync(FULL, psi, q ^ 8, 16);
        float xc = __shfl_sync(FULL, psi, q ^ 12, 16);
        psi = cc * x0 - Ap * xa - Bm * xb + Cpm * xc;
    }
    // S5: cnot(3,1) + h(3)
    {
        float x0 = __shfl_sync(FULL, psi, p31, 16);
        float x1 = __shfl_sync(FULL, psi, p31b, 16);
        psi = h3d * x0 + R_SQ2 * x1;
    }
    // S6: cnot(0,3) + [ry-(1); ry+(0)]
    {
        float x0 = __shfl_sync(FULL, psi, p03, 16);
        float xa = __shfl_sync(FULL, psi, p03 ^ 4, 16);
        float xb = __shfl_sync(FULL, psi, p03_8, 16);
        float xc = __shfl_sync(FULL, psi, p03_8 ^ 4, 16);
        psi = cc * x0 - Ap * xa - Bm * xb + Cpm * xc;
    }

    // ---- energy: E_i = psi_i * sum_m w_m(i) psi_{i^m}, masks {0,1,5,8,12,13} ----
    float p1  = __shfl_xor_sync(FULL, psi, 1, 16);
    float p5  = __shfl_xor_sync(FULL, psi, 5, 16);
    float p8  = __shfl_xor_sync(FULL, psi, 8, 16);
    float p12 = __shfl_xor_sync(FULL, psi, 12, 16);
    float p13 = __shfl_xor_sync(FULL, psi, 13, 16);
    float E = psi * (w0 * psi + w1 * p1 + w5 * p5 + w8 * p8 + w12 * p12 + w13 * p13);

    // butterfly reduce within the 16-lane group
    E += __shfl_xor_sync(FULL, E, 1, 16);
    E += __shfl_xor_sync(FULL, E, 2, 16);
    E += __shfl_xor_sync(FULL, E, 4, 16);
    E += __shfl_xor_sync(FULL, E, 8, 16);

    if (threadIdx.x == 0)
        out[0] = E - 0.042072551947440084f;
}

extern "C" void kernel_launch(void* const* d_in, const int* in_sizes, int n_in,
                              void* d_out, int out_size) {
    const float* phi = (const float*)d_in[0];
    float* out = (float*)d_out;
    vqe_energy_kernel<<<1, 32>>>(phi, out);
}

// round 5
// speedup vs baseline: 1.0530x; 1.0530x over previous
#include <cuda_runtime.h>

// 4-qubit VQE energy, warp-parallel, Clifford-folded, H-layers fused into
// neighboring RY layers (8-source shuffle steps).
// lane = q0*8 + q1*4 + q2*2 + q3. All gates real => psi real.

#define FULL 0xffffffffu
#define R_SQ2 0.70710678118654752f

__device__ __forceinline__ int P03(int x) { return x ^ ((x >> 3) & 1); }   // cnot(0,3)
__device__ __forceinline__ int P31(int x) { return x ^ ((x & 1) << 2); }   // cnot(3,1)

__global__ void vqe_energy_kernel(const float* __restrict__ phi_in,
                                  float* __restrict__ out) {
    const int lane = threadIdx.x & 15;

    // ---- per-lane index maps (ALU, overlaps the phi LDG) ----
    // M1 = [cnot(3,1); ry+(1); ry-(0)] ∘ [cnot(0,3); h(3)]
    const int A0 = P03(P31(lane));
    // S4 perm: cnot(2,1); cnot(2,0)
    const int q4 = lane ^ ((lane & 2) ? 12 : 0);
    // M2 = [cnot(0,3); ry-(1); ry+(0)] ∘ [cnot(3,1); h(3)]
    const int j0 = P03(lane);
    const int j2 = P03(lane ^ 8);
    const int C0 = P31(j0),     D0 = P31(j0 ^ 1);
    const int C1 = P31(j0 ^ 4), D1 = P31(j0 ^ 5);
    const int C2 = P31(j2),     D2 = P31(j2 ^ 1);
    const int C3 = P31(j2 ^ 4), D3 = P31(j2 ^ 5);

    // ---- per-lane observable weights (trailing Cliffords conjugated in) ----
    const float s0 = (lane & 8) ? -1.f : 1.f;
    const float s1 = (lane & 4) ? -1.f : 1.f;
    const float s2 = (lane & 2) ? -1.f : 1.f;
    const float s01  = s0 * s1;
    const float s012 = s01 * s2;
    const float w0  = 0.1777135822909176f * s01 + 0.12293330449299354f * s2;
    const float w1  = 0.1676833885560135f * s2 + 0.17627661394181787f;
    const float w5  = 0.04475008406301996f * (s0 * s2 - s0);
    const float w8  = 0.04475008406301996f * (s1 - s1 * s2);
    const float w12 = 0.1777135822909176f - 0.24274501260941383f * s2
                    + 0.17059759276836806f * s01 + 0.1676833885560135f * s012;
    const float w13 = -0.24274501260941383f * s2 + 0.12293330449299354f * s012;

    // H diagonal signs for the fused steps
    const float h3 = (lane & 1) ? -R_SQ2 : R_SQ2;      // uniform sign in M1
    const float hA = (j0 & 1) ? -R_SQ2 : R_SQ2;        // M2, sources e=0,4
    const float hB = -hA;                              // M2, sources e=8,12

    // ---- phi-dependent coefficients ----
    const float phi = phi_in[0];
    float s, c;
    __sincosf(phi * 0.0625f, &s, &c);                  // half-angle of ry(phi/8)
    const float cc  = c * c;
    const float o1p = (lane & 4) ?  s : -s;            // ry+(q1) off-diag
    const float o0m = (lane & 8) ? -s :  s;            // ry-(q0) off-diag
    const float Ap  = o1p * c;
    const float Bm  = c * o0m;
    const float Cpm = o1p * o0m;

    // ---- init (leading Cliffords folded): +1/2 @ {6,7}, -1/2 @ {10,11} ----
    float psi = 0.f;
    {
        const int g = lane >> 1;
        if (g == 3) psi = 0.5f;
        if (g == 5) psi = -0.5f;
    }

    // S1: ry+(1); ry-(0)
    {
        float a = __shfl_xor_sync(FULL, psi, 4, 16);
        float b = __shfl_xor_sync(FULL, psi, 8, 16);
        float d = __shfl_xor_sync(FULL, psi, 12, 16);
        psi = cc * psi + Ap * a + Bm * b + Cpm * d;
    }
    // M1: fused [cnot(0,3); h3] then [cnot(3,1); ry+(1); ry-(0)]
    {
        float x0 = __shfl_sync(FULL, psi, A0,      16);
        float x4 = __shfl_sync(FULL, psi, A0 ^ 4,  16);
        float x9 = __shfl_sync(FULL, psi, A0 ^ 9,  16);
        float xD = __shfl_sync(FULL, psi, A0 ^ 13, 16);
        float y1 = __shfl_sync(FULL, psi, A0 ^ 1,  16);
        float y5 = __shfl_sync(FULL, psi, A0 ^ 5,  16);
        float y8 = __shfl_sync(FULL, psi, A0 ^ 8,  16);
        float yC = __shfl_sync(FULL, psi, A0 ^ 12, 16);
        psi = h3    * (cc * x0 + Ap * x4 + Bm * x9 + Cpm * xD)
            + R_SQ2 * (cc * y1 + Ap * y5 + Bm * y8 + Cpm * yC);
    }
    // S4: cnot(2,1); cnot(2,0) + [ry-(1); ry+(0)]
    {
        float x0 = __shfl_sync(FULL, psi, q4,      16);
        float xa = __shfl_sync(FULL, psi, q4 ^ 4,  16);
        float xb = __shfl_sync(FULL, psi, q4 ^ 8,  16);
        float xc = __shfl_sync(FULL, psi, q4 ^ 12, 16);
        psi = cc * x0 - Ap * xa - Bm * xb + Cpm * xc;
    }
    // M2: fused [cnot(3,1); h3] then [cnot(0,3); ry-(1); ry+(0)]
    {
        float c0 = __shfl_sync(FULL, psi, C0, 16);
        float d0 = __shfl_sync(FULL, psi, D0, 16);
        float c1 = __shfl_sync(FULL, psi, C1, 16);
        float d1 = __shfl_sync(FULL, psi, D1, 16);
        float c2 = __shfl_sync(FULL, psi, C2, 16);
        float d2 = __shfl_sync(FULL, psi, D2, 16);
        float c3 = __shfl_sync(FULL, psi, C3, 16);
        float d3 = __shfl_sync(FULL, psi, D3, 16);
        psi = cc  * (hA * c0 + R_SQ2 * d0)
            - Ap  * (hA * c1 + R_SQ2 * d1)
            - Bm  * (hB * c2 + R_SQ2 * d2)
            + Cpm * (hB * c3 + R_SQ2 * d3);
    }

    // ---- energy: E_i = psi_i * Σ_m w_m(i)·psi_{i^m}, masks {0,1,5,8,12,13} ----
    float p1  = __shfl_xor_sync(FULL, psi, 1, 16);
    float p5  = __shfl_xor_sync(FULL, psi, 5, 16);
    float p8  = __shfl_xor_sync(FULL, psi, 8, 16);
    float p12 = __shfl_xor_sync(FULL, psi, 12, 16);
    float p13 = __shfl_xor_sync(FULL, psi, 13, 16);
    float E = psi * (w0 * psi + w1 * p1 + w5 * p5 + w8 * p8 + w12 * p12 + w13 * p13);

    // butterfly reduce within the 16-lane group
    E += __shfl_xor_sync(FULL, E, 1, 16);
    E += __shfl_xor_sync(FULL, E, 2, 16);
    E += __shfl_xor_sync(FULL, E, 4, 16);
    E += __shfl_xor_sync(FULL, E, 8, 16);

    if (threadIdx.x == 0)
        out[0] = E - 0.042072551947440084f;
}

extern "C" void kernel_launch(void* const* d_in, const int* in_sizes, int n_in,
                              void* d_out, int out_size) {
    const float* phi = (const float*)d_in[0];
    float* out = (float*)d_out;
    vqe_energy_kernel<<<1, 32>>>(phi, out);
}